// round 14
// baseline (speedup 1.0000x reference)
#include <cuda_runtime.h>
#include <cuda_bf16.h>
#include <cstdint>
#include <math.h>

// Problem constants
#define VOCAB 50257
#define EMB   16
#define BS    8
#define MCW   512
#define NTOK  (BS * MCW)      // 4096 tokens

// logits GEMM config (3x bf16 split, mma.sync m16n8k16)
#define KP      48            // K': [a_h1|a_h2|a_h1] x [b_h1|b_h1|b_h2]
#define KSTEPS  3             // KP / 16
#define NTILE   256           // N per block
#define NBLK_N  197           // ceil(50257/256)
#define PADV    (NBLK_N * NTILE)   // 50432
#define MTILE   128           // M per block
#define NBLK_M  (NTOK / MTILE)     // 32
#define ASTRIDE 28            // smem row stride in uint32 (conflict-free frag reads)

// Scratch (device globals: allocation-free)
__device__ float g_Q[NTOK * EMB];
__device__ float g_K[NTOK * EMB];
__device__ float g_V[NTOK * EMB];
__device__ float g_Wt[BS * MCW * MCW];            // g_Wt[b][k][q]
__device__ __nv_bfloat16 g_Ap[NTOK * KP];         // A' rows: [h1|h2|h1]
__device__ uint2 g_Bf[(PADV / 8) * KSTEPS * 32];  // B fragments, lane-coalesced

// ---------------------------------------------------------------------------
__device__ __forceinline__ uint32_t pkbf(__nv_bfloat16 lo, __nv_bfloat16 hi) {
    return ((uint32_t)__bfloat16_as_ushort(hi) << 16) | (uint32_t)__bfloat16_as_ushort(lo);
}

__device__ __forceinline__ void mma_bf16_k16(float* c,
                                             uint32_t a0, uint32_t a1, uint32_t a2, uint32_t a3,
                                             uint32_t b0, uint32_t b1) {
    asm volatile(
        "mma.sync.aligned.m16n8k16.row.col.f32.bf16.bf16.f32 "
        "{%0,%1,%2,%3}, {%4,%5,%6,%7}, {%8,%9}, {%0,%1,%2,%3};"
        : "+f"(c[0]), "+f"(c[1]), "+f"(c[2]), "+f"(c[3])
        : "r"(a0), "r"(a1), "r"(a2), "r"(a3), "r"(b0), "r"(b1));
}

// ---------------------------------------------------------------------------
// Kernel 0: build fragment-ready bf16 B table.
// B'[v][k]: ks<2 -> b_h1[k%16]; ks==2 -> b_h2[k%16].
// Fragment for (nblk, ks), lane = grp*4+tidg, grp = v&7:
//   .x = pack(B'[16ks+2tidg], B'[16ks+2tidg+1]), .y = pack(+8 pair)
// ---------------------------------------------------------------------------
__global__ void prep_b_kernel(const float* __restrict__ Wl) {
    int v = blockIdx.x * 256 + threadIdx.x;
    if (v >= PADV) return;

    __nv_bfloat16 b1[16], b2[16];
    if (v < VOCAB) {
#pragma unroll
        for (int k = 0; k < 16; ++k) {
            float w = Wl[v * 16 + k];
            b1[k] = __float2bfloat16(w);
            b2[k] = __float2bfloat16(w - __bfloat162float(b1[k]));
        }
    } else {
#pragma unroll
        for (int k = 0; k < 16; ++k) { b1[k] = __float2bfloat16(0.f); b2[k] = __float2bfloat16(0.f); }
    }

    size_t base = ((size_t)(v >> 3) * KSTEPS) * 32 + (size_t)(v & 7) * 4;
#pragma unroll
    for (int ks = 0; ks < KSTEPS; ++ks) {
        const __nv_bfloat16* src = (ks < 2) ? b1 : b2;
#pragma unroll
        for (int tg = 0; tg < 4; ++tg) {
            uint2 f;
            f.x = pkbf(src[2 * tg],     src[2 * tg + 1]);
            f.y = pkbf(src[2 * tg + 8], src[2 * tg + 9]);
            g_Bf[base + (size_t)ks * 32 + tg] = f;
        }
    }
}

// ---------------------------------------------------------------------------
// Kernel 1: embedding gather + Q/K/V projections
// ---------------------------------------------------------------------------
__global__ void qkv_kernel(const int* __restrict__ x,
                           const float* __restrict__ emb_table,
                           const float* __restrict__ Wq, const float* __restrict__ bq,
                           const float* __restrict__ Wk, const float* __restrict__ bk,
                           const float* __restrict__ Wv, const float* __restrict__ bv) {
    __shared__ float semb[16][EMB];
    int lt = threadIdx.x >> 4;
    int e  = threadIdx.x & 15;
    int tok = blockIdx.x * 16 + lt;
    int id = x[tok];
    semb[lt][e] = emb_table[id * EMB + e];
    __syncthreads();

    float q = bq[e], k = bk[e], v = bv[e];
#pragma unroll
    for (int j = 0; j < EMB; ++j) {
        float ej = semb[lt][j];
        q = fmaf(Wq[e * EMB + j], ej, q);
        k = fmaf(Wk[e * EMB + j], ej, k);
        v = fmaf(Wv[e * EMB + j], ej, v);
    }
    g_Q[tok * EMB + e] = q;
    g_K[tok * EMB + e] = k;
    g_V[tok * EMB + e] = v;
}

// ---------------------------------------------------------------------------
// Kernel 2: scores + mask + zero->-inf quirk + softmax over QUERY axis
// ---------------------------------------------------------------------------
__global__ void attn_weights_kernel() {
    int kc0  = blockIdx.x * 8;
    int b    = blockIdx.y;
    int tid  = threadIdx.x;
    int wid  = tid >> 5;
    int lane = tid & 31;

    __shared__ float sK[8][EMB];
    __shared__ float sredM[16][8];
    __shared__ float sredS[16][8];
    __shared__ float sfinM[8];
    __shared__ float sfinS[8];

    const float4* qrow = reinterpret_cast<const float4*>(g_Q + (b * MCW + tid) * EMB);
    float4 q0 = qrow[0], q1 = qrow[1], q2 = qrow[2], q3 = qrow[3];

    if (tid < 8 * EMB) {
        sK[tid >> 4][tid & 15] = g_K[(b * MCW + kc0 + (tid >> 4)) * EMB + (tid & 15)];
    }
    __syncthreads();

    float val[8];
#pragma unroll
    for (int kc = 0; kc < 8; ++kc) {
        const float* kv = sK[kc];
        float s = 0.0f;
        s = fmaf(q0.x, kv[0],  s); s = fmaf(q0.y, kv[1],  s);
        s = fmaf(q0.z, kv[2],  s); s = fmaf(q0.w, kv[3],  s);
        s = fmaf(q1.x, kv[4],  s); s = fmaf(q1.y, kv[5],  s);
        s = fmaf(q1.z, kv[6],  s); s = fmaf(q1.w, kv[7],  s);
        s = fmaf(q2.x, kv[8],  s); s = fmaf(q2.y, kv[9],  s);
        s = fmaf(q2.z, kv[10], s); s = fmaf(q2.w, kv[11], s);
        s = fmaf(q3.x, kv[12], s); s = fmaf(q3.y, kv[13], s);
        s = fmaf(q3.z, kv[14], s); s = fmaf(q3.w, kv[15], s);
        val[kc] = ((kc0 + kc) <= tid && s != 0.0f) ? s : -INFINITY;
    }

#pragma unroll
    for (int kc = 0; kc < 8; ++kc) {
        float v = val[kc];
#pragma unroll
        for (int o = 16; o > 0; o >>= 1) v = fmaxf(v, __shfl_xor_sync(0xffffffffu, v, o));
        if (lane == 0) sredM[wid][kc] = v;
    }
    __syncthreads();
    if (tid < 8) {
        float m = -INFINITY;
#pragma unroll
        for (int w = 0; w < 16; ++w) m = fmaxf(m, sredM[w][tid]);
        sfinM[tid] = m;
    }
    __syncthreads();

    float p[8];
#pragma unroll
    for (int kc = 0; kc < 8; ++kc) {
        p[kc] = __expf(val[kc] - sfinM[kc]);
        float v = p[kc];
#pragma unroll
        for (int o = 16; o > 0; o >>= 1) v += __shfl_xor_sync(0xffffffffu, v, o);
        if (lane == 0) sredS[wid][kc] = v;
    }
    __syncthreads();
    if (tid < 8) {
        float s = 0.0f;
#pragma unroll
        for (int w = 0; w < 16; ++w) s += sredS[w][tid];
        sfinS[tid] = s;
    }
    __syncthreads();

#pragma unroll
    for (int kc = 0; kc < 8; ++kc) {
        float w = p[kc] / sfinS[kc];
        g_Wt[((size_t)(b * MCW + kc0 + kc)) * MCW + tid] = w;
    }
}

// ---------------------------------------------------------------------------
// Kernel 3: out = weights @ V, written directly as bf16-split A' rows
// ---------------------------------------------------------------------------
__global__ void attn_out_kernel() {
    int b  = blockIdx.y;
    int w  = blockIdx.x * 16 + (threadIdx.x & 15);
    int e  = threadIdx.x >> 4;

    __shared__ float sV[MCW * EMB];
    const float* Vb = g_V + b * MCW * EMB;
    for (int i = threadIdx.x; i < MCW * EMB; i += 256) sV[i] = Vb[i];
    __syncthreads();

    const float* Wtb = g_Wt + (size_t)b * MCW * MCW;
    float acc = 0.0f;
#pragma unroll 16
    for (int p = 0; p < MCW; ++p)
        acc = fmaf(Wtb[p * MCW + w], sV[p * EMB + e], acc);

    int tok = b * MCW + w;
    __nv_bfloat16 h1 = __float2bfloat16(acc);
    __nv_bfloat16 h2 = __float2bfloat16(acc - __bfloat162float(h1));
    g_Ap[tok * KP + e]      = h1;
    g_Ap[tok * KP + 16 + e] = h2;
    g_Ap[tok * KP + 32 + e] = h1;
}

// ---------------------------------------------------------------------------
// Kernel 4: logits GEMM (mma.sync m16n8k16 bf16, 3x split)
// grid: (32 M-blocks, 197 N-blocks); block: 256 thr = 8 warps.
// B fragments coalesced (uint2/lane); A' packed-pair smem, stride-28 rows.
// Epilogue: SCALAR stores (row*VOCAB is odd-strided; float2 would misalign).
// ---------------------------------------------------------------------------
__global__ void __launch_bounds__(256)
logits_mma_kernel(const float* __restrict__ bl, float* __restrict__ logits) {
    __shared__ uint32_t sA[MTILE * ASTRIDE];   // 14336 B

    int tid  = threadIdx.x;
    int warp = tid >> 5;
    int lane = tid & 31;
    int grp  = lane >> 2;     // 0..7
    int tidg = lane & 3;      // 0..3

    int mbase = blockIdx.x * MTILE;
    int nwarp = blockIdx.y * NTILE + warp * 32;

    // --- B fragments: coalesced LDG.64 (lane L -> element L)
    uint2 breg[4][KSTEPS];
#pragma unroll
    for (int nt = 0; nt < 4; ++nt) {
        size_t nb = ((size_t)(nwarp >> 3) + nt) * KSTEPS;
#pragma unroll
        for (int ks = 0; ks < KSTEPS; ++ks)
            breg[nt][ks] = g_Bf[(nb + ks) * 32 + lane];
    }

    // --- bias (col0 even, bl base aligned -> float2 load safe)
    float2 biasv[4];
#pragma unroll
    for (int nt = 0; nt < 4; ++nt) {
        int c0 = nwarp + nt * 8 + 2 * tidg;
        if (c0 + 1 < VOCAB)      biasv[nt] = *reinterpret_cast<const float2*>(bl + c0);
        else if (c0 < VOCAB)     biasv[nt] = make_float2(bl[c0], 0.0f);
        else                     biasv[nt] = make_float2(0.0f, 0.0f);
    }

    // --- stage A' tile: 128 rows x 24 uint32 (96B), 12 uint2 per row
    for (int i = tid; i < MTILE * 12; i += 256) {
        int row = i / 12;
        int h   = i % 12;
        uint2 v = reinterpret_cast<const uint2*>(g_Ap + (size_t)(mbase + row) * KP)[h];
        *reinterpret_cast<uint2*>(&sA[row * ASTRIDE + h * 2]) = v;
    }
    __syncthreads();

#pragma unroll 1
    for (int msub = 0; msub < MTILE / 16; ++msub) {
        float c[4][4] = {{0.f,0.f,0.f,0.f},{0.f,0.f,0.f,0.f},
                         {0.f,0.f,0.f,0.f},{0.f,0.f,0.f,0.f}};
        int ar = msub * 16 + grp;
#pragma unroll
        for (int ks = 0; ks < KSTEPS; ++ks) {
            int kb = ks * 8 + tidg;     // pair index
            uint32_t a0 = sA[ar * ASTRIDE + kb];
            uint32_t a1 = sA[(ar + 8) * ASTRIDE + kb];
            uint32_t a2 = sA[ar * ASTRIDE + kb + 4];
            uint32_t a3 = sA[(ar + 8) * ASTRIDE + kb + 4];
#pragma unroll
            for (int nt = 0; nt < 4; ++nt)
                mma_bf16_k16(c[nt], a0, a1, a2, a3, breg[nt][ks].x, breg[nt][ks].y);
        }

        int row0 = mbase + msub * 16 + grp;
        size_t rb0 = (size_t)row0 * VOCAB;
        size_t rb1 = rb0 + (size_t)8 * VOCAB;
#pragma unroll
        for (int nt = 0; nt < 4; ++nt) {
            int col0 = nwarp + nt * 8 + 2 * tidg;
            if (col0 < VOCAB) {
                logits[rb0 + col0] = c[nt][0] + biasv[nt].x;
                logits[rb1 + col0] = c[nt][2] + biasv[nt].x;
            }
            if (col0 + 1 < VOCAB) {
                logits[rb0 + col0 + 1] = c[nt][1] + biasv[nt].y;
                logits[rb1 + col0 + 1] = c[nt][3] + biasv[nt].y;
            }
        }
    }
}

// ---------------------------------------------------------------------------
extern "C" void kernel_launch(void* const* d_in, const int* in_sizes, int n_in,
                              void* d_out, int out_size) {
    const int*   x         = (const int*)  d_in[0];
    const float* emb_table = (const float*)d_in[1];
    const float* Wq        = (const float*)d_in[2];
    const float* bq        = (const float*)d_in[3];
    const float* Wk        = (const float*)d_in[4];
    const float* bk        = (const float*)d_in[5];
    const float* Wv        = (const float*)d_in[6];
    const float* bv        = (const float*)d_in[7];
    const float* Wl        = (const float*)d_in[8];
    const float* bl        = (const float*)d_in[9];
    float* logits          = (float*)d_out;

    prep_b_kernel<<<(PADV + 255) / 256, 256>>>(Wl);

    qkv_kernel<<<NTOK / 16, 256>>>(x, emb_table, Wq, bq, Wk, bk, Wv, bv);

    dim3 g2(MCW / 8, BS);
    attn_weights_kernel<<<g2, MCW>>>();

    dim3 g3(MCW / 16, BS);
    attn_out_kernel<<<g3, 256>>>();

    dim3 g4(NBLK_M, NBLK_N);
    logits_mma_kernel<<<g4, 256>>>(bl, logits);
}

// round 16
// speedup vs baseline: 2.4518x; 2.4518x over previous
#include <cuda_runtime.h>
#include <math.h>

// Problem constants
#define VOCAB 50257
#define EMB   16
#define BS    8
#define MCW   512
#define NTOK  (BS * MCW)      // 4096 tokens

// Scratch (device globals: allocation-free)
__device__ float g_Q[NTOK * EMB];
__device__ float g_K[NTOK * EMB];
__device__ float g_V[NTOK * EMB];
__device__ float g_Wt[BS * MCW * MCW];   // g_Wt[b][k][q] : softmaxed weight (b,q,k), k-major
__device__ float g_out[NTOK * EMB];

// ---------------------------------------------------------------------------
// packed fp32x2 helpers (float2 constraints — proven no-spill form from R7)
// ---------------------------------------------------------------------------
__device__ __forceinline__ float2 fma2(float2 a, float2 b, float2 c) {
    float2 d;
    asm("{\n\t"
        ".reg .b64 ra, rb, rc, rd;\n\t"
        "mov.b64 ra, {%2, %3};\n\t"
        "mov.b64 rb, {%4, %5};\n\t"
        "mov.b64 rc, {%6, %7};\n\t"
        "fma.rn.f32x2 rd, ra, rb, rc;\n\t"
        "mov.b64 {%0, %1}, rd;\n\t"
        "}"
        : "=f"(d.x), "=f"(d.y)
        : "f"(a.x), "f"(a.y), "f"(b.x), "f"(b.y), "f"(c.x), "f"(c.y));
    return d;
}

__device__ __forceinline__ float2 add2(float2 a, float2 b) {
    float2 d;
    asm("{\n\t"
        ".reg .b64 ra, rb, rd;\n\t"
        "mov.b64 ra, {%2, %3};\n\t"
        "mov.b64 rb, {%4, %5};\n\t"
        "add.rn.f32x2 rd, ra, rb;\n\t"
        "mov.b64 {%0, %1}, rd;\n\t"
        "}"
        : "=f"(d.x), "=f"(d.y)
        : "f"(a.x), "f"(a.y), "f"(b.x), "f"(b.y));
    return d;
}

// ---------------------------------------------------------------------------
// Kernel 1: embedding gather + Q/K/V projections
// ---------------------------------------------------------------------------
__global__ void qkv_kernel(const int* __restrict__ x,
                           const float* __restrict__ emb_table,
                           const float* __restrict__ Wq, const float* __restrict__ bq,
                           const float* __restrict__ Wk, const float* __restrict__ bk,
                           const float* __restrict__ Wv, const float* __restrict__ bv) {
    __shared__ float semb[16][EMB];
    int lt = threadIdx.x >> 4;     // local token 0..15
    int e  = threadIdx.x & 15;     // output dim
    int tok = blockIdx.x * 16 + lt;
    int id = x[tok];
    semb[lt][e] = emb_table[id * EMB + e];
    __syncthreads();

    float q = bq[e], k = bk[e], v = bv[e];
#pragma unroll
    for (int j = 0; j < EMB; ++j) {
        float ej = semb[lt][j];
        q = fmaf(Wq[e * EMB + j], ej, q);
        k = fmaf(Wk[e * EMB + j], ej, k);
        v = fmaf(Wv[e * EMB + j], ej, v);
    }
    g_Q[tok * EMB + e] = q;
    g_K[tok * EMB + e] = k;
    g_V[tok * EMB + e] = v;
}

// ---------------------------------------------------------------------------
// Kernel 2: scores + mask + zero->-inf quirk + softmax over QUERY axis
// grid: (MCW/8, BS); block: 512 threads (q). Batched reductions (R9 version:
// all 8 k-columns reduced together -> 4 syncthreads instead of 48).
// ---------------------------------------------------------------------------
__global__ void attn_weights_kernel() {
    int kc0  = blockIdx.x * 8;
    int b    = blockIdx.y;
    int tid  = threadIdx.x;   // q index
    int wid  = tid >> 5;
    int lane = tid & 31;

    __shared__ float sK[8][EMB];
    __shared__ float sredM[16][8];
    __shared__ float sredS[16][8];
    __shared__ float sfinM[8];
    __shared__ float sfinS[8];

    const float4* qrow = reinterpret_cast<const float4*>(g_Q + (b * MCW + tid) * EMB);
    float4 q0 = qrow[0], q1 = qrow[1], q2 = qrow[2], q3 = qrow[3];

    if (tid < 8 * EMB) {
        sK[tid >> 4][tid & 15] = g_K[(b * MCW + kc0 + (tid >> 4)) * EMB + (tid & 15)];
    }
    __syncthreads();

    float val[8];
#pragma unroll
    for (int kc = 0; kc < 8; ++kc) {
        const float* kv = sK[kc];
        float s = 0.0f;
        s = fmaf(q0.x, kv[0],  s); s = fmaf(q0.y, kv[1],  s);
        s = fmaf(q0.z, kv[2],  s); s = fmaf(q0.w, kv[3],  s);
        s = fmaf(q1.x, kv[4],  s); s = fmaf(q1.y, kv[5],  s);
        s = fmaf(q1.z, kv[6],  s); s = fmaf(q1.w, kv[7],  s);
        s = fmaf(q2.x, kv[8],  s); s = fmaf(q2.y, kv[9],  s);
        s = fmaf(q2.z, kv[10], s); s = fmaf(q2.w, kv[11], s);
        s = fmaf(q3.x, kv[12], s); s = fmaf(q3.y, kv[13], s);
        s = fmaf(q3.z, kv[14], s); s = fmaf(q3.w, kv[15], s);
        // mask: keep only k <= q ; quirk: exact-zero scores -> -inf
        val[kc] = ((kc0 + kc) <= tid && s != 0.0f) ? s : -INFINITY;
    }

    // batched max reduction over q for all 8 columns
#pragma unroll
    for (int kc = 0; kc < 8; ++kc) {
        float v = val[kc];
#pragma unroll
        for (int o = 16; o > 0; o >>= 1) v = fmaxf(v, __shfl_xor_sync(0xffffffffu, v, o));
        if (lane == 0) sredM[wid][kc] = v;
    }
    __syncthreads();
    if (tid < 8) {
        float m = -INFINITY;
#pragma unroll
        for (int w = 0; w < 16; ++w) m = fmaxf(m, sredM[w][tid]);
        sfinM[tid] = m;
    }
    __syncthreads();

    float p[8];
#pragma unroll
    for (int kc = 0; kc < 8; ++kc) {
        p[kc] = __expf(val[kc] - sfinM[kc]);
        float v = p[kc];
#pragma unroll
        for (int o = 16; o > 0; o >>= 1) v += __shfl_xor_sync(0xffffffffu, v, o);
        if (lane == 0) sredS[wid][kc] = v;
    }
    __syncthreads();
    if (tid < 8) {
        float s = 0.0f;
#pragma unroll
        for (int w = 0; w < 16; ++w) s += sredS[w][tid];
        sfinS[tid] = s;
    }
    __syncthreads();

#pragma unroll
    for (int kc = 0; kc < 8; ++kc) {
        float w = p[kc] / sfinS[kc];
        g_Wt[((size_t)(b * MCW + kc0 + kc)) * MCW + tid] = w;   // coalesced over q
    }
}

// ---------------------------------------------------------------------------
// Kernel 3: out[b,w,e] = sum_p Wt[b][p][w] * V[b,p,e]   (unroll 16: deep LDG MLP)
// ---------------------------------------------------------------------------
__global__ void attn_out_kernel() {
    int b  = blockIdx.y;
    int w  = blockIdx.x * 16 + (threadIdx.x & 15);
    int e  = threadIdx.x >> 4;

    __shared__ float sV[MCW * EMB];
    const float* Vb = g_V + b * MCW * EMB;
    for (int i = threadIdx.x; i < MCW * EMB; i += 256) sV[i] = Vb[i];
    __syncthreads();

    const float* Wtb = g_Wt + (size_t)b * MCW * MCW;
    float acc = 0.0f;
#pragma unroll 16
    for (int p = 0; p < MCW; ++p)
        acc = fmaf(Wtb[p * MCW + w], sV[p * EMB + e], acc);

    g_out[(b * MCW + w) * EMB + e] = acc;
}

// ---------------------------------------------------------------------------
// Kernel 4: logits[t, v] = dot(out[t,:], Wl[v,:]) + bl[v]   (R7 verbatim)
// Dup-quad smem staging, float2 fma2, 4 chains depth 8;
// coalesced row mapping {v, v+256, v+512, v+768}; token loop unroll 2.
// ---------------------------------------------------------------------------
#define TC  256      // tokens per block
#define VB  1024     // vocab per block (256 threads * 4 rows)

__global__ void __launch_bounds__(256, 2)
logits_kernel(const float* __restrict__ Wl, const float* __restrict__ bl,
              float* __restrict__ logits) {
    __shared__ float4 stok[TC * 8];   // 32 KB : stok[t*8+j] = (t[2j],t[2j],t[2j+1],t[2j+1])

    int tid   = threadIdx.x;
    int t0    = blockIdx.y * TC;
    int vbase = blockIdx.x * VB;

    // stage dup-quad token vectors
    const float2* src = reinterpret_cast<const float2*>(g_out + t0 * EMB);
    for (int i = tid; i < TC * 8; i += 256) {
        float2 v = src[i];
        stok[i] = make_float4(v.x, v.x, v.y, v.y);
    }

    // this thread's 4 vocab rows (lane-consecutive within each group of 256)
    int v0 = vbase + tid;          // row A
    int v1 = v0 + 256;             // row B   (pair0 = A,B)
    int v2 = v0 + 512;             // row C
    int v3 = v0 + 768;             // row D   (pair1 = C,D)

    bool a0 = (v0 < VOCAB), a1 = (v1 < VOCAB);
    bool c0 = (v2 < VOCAB), c1 = (v3 < VOCAB);

    float2 wl0[EMB], wl1[EMB];
#pragma unroll
    for (int k = 0; k < EMB; ++k) {
        wl0[k] = make_float2(a0 ? Wl[v0 * EMB + k] : 0.0f,
                             a1 ? Wl[v1 * EMB + k] : 0.0f);
        wl1[k] = make_float2(c0 ? Wl[v2 * EMB + k] : 0.0f,
                             c1 ? Wl[v3 * EMB + k] : 0.0f);
    }
    float2 b0 = make_float2(a0 ? bl[v0] : 0.0f, a1 ? bl[v1] : 0.0f);
    float2 b1 = make_float2(c0 ? bl[v2] : 0.0f, c1 ? bl[v3] : 0.0f);

    __syncthreads();

#pragma unroll 2
    for (int t = 0; t < TC; ++t) {
        const float4* tk = stok + t * 8;
        // 4 independent chains, depth 8
        float2 p00 = b0;
        float2 p01 = make_float2(0.0f, 0.0f);
        float2 p10 = b1;
        float2 p11 = make_float2(0.0f, 0.0f);
#pragma unroll
        for (int j = 0; j < 8; ++j) {
            float4 tv = tk[j];
            float2 ta = make_float2(tv.x, tv.y);   // dup of t[2j]
            float2 tb = make_float2(tv.z, tv.w);   // dup of t[2j+1]
            p00 = fma2(wl0[2 * j],     ta, p00);
            p01 = fma2(wl0[2 * j + 1], tb, p01);
            p10 = fma2(wl1[2 * j],     ta, p10);
            p11 = fma2(wl1[2 * j + 1], tb, p11);
        }
        float2 acc0 = add2(p00, p01);   // (logit[v0], logit[v1])
        float2 acc1 = add2(p10, p11);   // (logit[v2], logit[v3])

        size_t base = (size_t)(t0 + t) * VOCAB;
        // lane-consecutive -> fully coalesced STG.32
        if (a0) logits[base + v0] = acc0.x;
        if (a1) logits[base + v1] = acc0.y;
        if (c0) logits[base + v2] = acc1.x;
        if (c1) logits[base + v3] = acc1.y;
    }
}

// ---------------------------------------------------------------------------
extern "C" void kernel_launch(void* const* d_in, const int* in_sizes, int n_in,
                              void* d_out, int out_size) {
    const int*   x         = (const int*)  d_in[0];
    const float* emb_table = (const float*)d_in[1];
    const float* Wq        = (const float*)d_in[2];
    const float* bq        = (const float*)d_in[3];
    const float* Wk        = (const float*)d_in[4];
    const float* bk        = (const float*)d_in[5];
    const float* Wv        = (const float*)d_in[6];
    const float* bv        = (const float*)d_in[7];
    const float* Wl        = (const float*)d_in[8];
    const float* bl        = (const float*)d_in[9];
    float* logits          = (float*)d_out;

    qkv_kernel<<<NTOK / 16, 256>>>(x, emb_table, Wq, bq, Wk, bk, Wv, bv);

    dim3 g2(MCW / 8, BS);
    attn_weights_kernel<<<g2, MCW>>>();

    dim3 g3(MCW / 16, BS);
    attn_out_kernel<<<g3, 256>>>();

    dim3 g4((VOCAB + VB - 1) / VB, NTOK / TC);
    logits_kernel<<<g4, 256>>>(Wl, bl, logits);
}